// round 3
// baseline (speedup 1.0000x reference)
#include <cuda_runtime.h>
#include <cuda_bf16.h>

#define NN 100000
#define EE 640000
#define HH 128
#define GG 64
#define CC 7

// ---------------- device scratch (no allocation allowed) ----------------
__device__ int   g_deg[NN];
__device__ float g_dinv[NN];
__device__ int   g_rowptr[NN + 1];
__device__ int   g_cursor[NN];
__device__ int   g_src[EE];
__device__ float g_w[EE];
__device__ float g_hA[(size_t)NN * HH];
__device__ float g_hB[(size_t)NN * HH];
__device__ float g_pool[GG * HH];
__device__ int   g_cnt[GG];

// ---------------- helpers ----------------
__device__ __forceinline__ float4 f4_fma(float a, float4 v, float4 acc) {
    acc.x += a * v.x; acc.y += a * v.y; acc.z += a * v.z; acc.w += a * v.w;
    return acc;
}

// ---------------- init: deg=1 (self loop), cnt=0 ----------------
__global__ void init_kernel() {
    int i = blockIdx.x * blockDim.x + threadIdx.x;
    if (i < NN) g_deg[i] = 1;
    if (i < GG) g_cnt[i] = 0;
}

// ---------------- in-degree count ----------------
__global__ void deg_kernel(const int* __restrict__ col) {
    int e = blockIdx.x * blockDim.x + threadIdx.x;
    if (e < EE) atomicAdd(&g_deg[col[e]], 1);
}

// ---------------- dinv + per-graph node counts ----------------
__global__ void dinv_kernel(const int* __restrict__ batch) {
    int i = blockIdx.x * blockDim.x + threadIdx.x;
    if (i < NN) {
        g_dinv[i] = rsqrtf((float)g_deg[i]);
        atomicAdd(&g_cnt[batch[i]], 1);
    }
}

// ---------------- exclusive prefix scan of in-degree -> rowptr/cursor ----------------
__global__ void scan_kernel() {
    __shared__ int tsum[1024];
    const int t = threadIdx.x;
    const int CH = (NN + 1023) / 1024;       // 98
    int lo = t * CH;
    int hi = lo + CH; if (hi > NN) hi = NN;
    int s = 0;
    for (int i = lo; i < hi; ++i) s += g_deg[i] - 1;
    tsum[t] = s;
    __syncthreads();
    // Hillis-Steele inclusive scan
    for (int off = 1; off < 1024; off <<= 1) {
        int v = (t >= off) ? tsum[t - off] : 0;
        __syncthreads();
        tsum[t] += v;
        __syncthreads();
    }
    int run = (t == 0) ? 0 : tsum[t - 1];
    for (int i = lo; i < hi; ++i) {
        g_rowptr[i] = run;
        g_cursor[i] = run;
        run += g_deg[i] - 1;
    }
    if (t == 1023) g_rowptr[NN] = tsum[1023];
}

// ---------------- CSR fill (bucket by destination) ----------------
__global__ void fill_kernel(const int* __restrict__ rowi, const int* __restrict__ coli) {
    int e = blockIdx.x * blockDim.x + threadIdx.x;
    if (e >= EE) return;
    int r = rowi[e], c = coli[e];
    int p = atomicAdd(&g_cursor[c], 1);
    g_src[p] = r;
    g_w[p]   = g_dinv[r] * g_dinv[c];
}

// ---------------- layer 1: scalar aggregation + outer product with W1 ----------------
__global__ void layer1_kernel(const float* __restrict__ x,
                              const float* __restrict__ W1,
                              const float* __restrict__ b1) {
    int warp = (blockIdx.x * blockDim.x + threadIdx.x) >> 5;
    int lane = threadIdx.x & 31;
    if (warp >= NN) return;
    const int i = warp;
    int ps = g_rowptr[i], pe = g_rowptr[i + 1];
    float s = 0.f;
    for (int p = ps + lane; p < pe; p += 32)
        s += g_w[p] * __ldg(x + g_src[p]);
    #pragma unroll
    for (int off = 16; off > 0; off >>= 1)
        s += __shfl_xor_sync(0xffffffffu, s, off);
    float di = g_dinv[i];
    s += di * di * __ldg(x + i);       // self loop
    float4 wv = ((const float4*)W1)[lane];
    float4 bv = ((const float4*)b1)[lane];
    float4 o;
    o.x = fmaxf(s * wv.x + bv.x, 0.f);
    o.y = fmaxf(s * wv.y + bv.y, 0.f);
    o.z = fmaxf(s * wv.z + bv.z, 0.f);
    o.w = fmaxf(s * wv.w + bv.w, 0.f);
    *(float4*)(g_hA + (size_t)i * HH + lane * 4) = o;
}

// ---------------- GEMM: C[N,128] = A[N,128] @ W[128,128]  (fp32, register-blocked) ----------------
#define GEMM_ROWS 64
#define TM 8
__global__ __launch_bounds__(256) void gemm_kernel(const float* __restrict__ A,
                                                   const float* __restrict__ W,
                                                   float* __restrict__ Cout) {
    extern __shared__ float sm[];
    float* Wsh = sm;                 // 128*128
    float* Ash = sm + HH * HH;       // 64*128
    const int tid = threadIdx.x;
    // load W (16384 floats)
    const float4* W4 = (const float4*)W;
    float4* Wsh4 = (float4*)Wsh;
    #pragma unroll
    for (int i = tid; i < HH * HH / 4; i += 256) Wsh4[i] = W4[i];
    // load A tile (64x128)
    const int block_row = blockIdx.x * GEMM_ROWS;
    const float4* A4 = (const float4*)(A + (size_t)block_row * HH);
    float4* Ash4 = (float4*)Ash;
    #pragma unroll
    for (int i = tid; i < GEMM_ROWS * HH / 4; i += 256) {
        int r = i / (HH / 4);
        Ash4[i] = (block_row + r < NN) ? A4[i] : make_float4(0.f, 0.f, 0.f, 0.f);
    }
    __syncthreads();

    const int ty = tid >> 5;         // 0..7  -> row group of 8
    const int tx = tid & 31;         // 0..31 -> 4 cols
    float4 acc[TM];
    #pragma unroll
    for (int i = 0; i < TM; ++i) acc[i] = make_float4(0.f, 0.f, 0.f, 0.f);
    const float* arow = Ash + (ty * TM) * HH;
    #pragma unroll 4
    for (int k = 0; k < HH; ++k) {
        float4 w = *(const float4*)(Wsh + k * HH + tx * 4);
        #pragma unroll
        for (int i = 0; i < TM; ++i) {
            float a = arow[i * HH + k];   // warp-broadcast LDS
            acc[i] = f4_fma(a, w, acc[i]);
        }
    }
    #pragma unroll
    for (int i = 0; i < TM; ++i) {
        int r = block_row + ty * TM + i;
        if (r < NN) *(float4*)(Cout + (size_t)r * HH + tx * 4) = acc[i];
    }
}

// ---------------- propagation: out[i] = relu?( sum_e w_e * hin[src] + dinv_i^2 * hin[i] + b ) ----------------
template <bool RELU>
__global__ void prop_kernel(const float* __restrict__ hin,
                            float* __restrict__ hout,
                            const float* __restrict__ bias) {
    int warp = (blockIdx.x * blockDim.x + threadIdx.x) >> 5;
    int lane = threadIdx.x & 31;
    if (warp >= NN) return;
    const int i = warp;
    const float di = g_dinv[i];
    float4 self = *(const float4*)(hin + (size_t)i * HH + lane * 4);
    const float w0 = di * di;
    float4 acc;
    acc.x = w0 * self.x; acc.y = w0 * self.y; acc.z = w0 * self.z; acc.w = w0 * self.w;
    int p = g_rowptr[i];
    const int pe = g_rowptr[i + 1];
    // 4-deep software pipeline for MLP
    for (; p + 3 < pe; p += 4) {
        int s0 = g_src[p], s1 = g_src[p + 1], s2 = g_src[p + 2], s3 = g_src[p + 3];
        float wa = g_w[p], wb = g_w[p + 1], wc = g_w[p + 2], wd = g_w[p + 3];
        float4 v0 = *(const float4*)(hin + (size_t)s0 * HH + lane * 4);
        float4 v1 = *(const float4*)(hin + (size_t)s1 * HH + lane * 4);
        float4 v2 = *(const float4*)(hin + (size_t)s2 * HH + lane * 4);
        float4 v3 = *(const float4*)(hin + (size_t)s3 * HH + lane * 4);
        acc = f4_fma(wa, v0, acc);
        acc = f4_fma(wb, v1, acc);
        acc = f4_fma(wc, v2, acc);
        acc = f4_fma(wd, v3, acc);
    }
    for (; p < pe; ++p) {
        int s0 = g_src[p];
        float wa = g_w[p];
        float4 v0 = *(const float4*)(hin + (size_t)s0 * HH + lane * 4);
        acc = f4_fma(wa, v0, acc);
    }
    float4 b = ((const float4*)bias)[lane];
    acc.x += b.x; acc.y += b.y; acc.z += b.z; acc.w += b.w;
    if (RELU) {
        acc.x = fmaxf(acc.x, 0.f); acc.y = fmaxf(acc.y, 0.f);
        acc.z = fmaxf(acc.z, 0.f); acc.w = fmaxf(acc.w, 0.f);
    }
    *(float4*)(hout + (size_t)i * HH + lane * 4) = acc;
}

// ---------------- mean pool per graph (batch is sorted -> contiguous ranges) ----------------
__global__ void pool_kernel() {
    const int g = blockIdx.x;
    int start = 0;
    #pragma unroll
    for (int j = 0; j < GG; ++j) if (j < g) start += g_cnt[j];
    const int cntg = g_cnt[g];
    const int t = threadIdx.x;          // 256
    const int col = t & 127;
    const int half = t >> 7;
    float s = 0.f;
    for (int r = start + half; r < start + cntg; r += 2)
        s += g_hA[(size_t)r * HH + col];
    __shared__ float red[256];
    red[t] = s;
    __syncthreads();
    if (half == 0) {
        float tot = red[t] + red[t + 128];
        g_pool[g * HH + col] = tot / fmaxf((float)cntg, 1.f);
    }
}

// ---------------- final linear: out[G,C] = pool @ Wl + bl ----------------
__global__ void final_kernel(const float* __restrict__ Wl,
                             const float* __restrict__ bl,
                             float* __restrict__ out) {
    int t = threadIdx.x;
    if (t >= GG * CC) return;
    int g = t / CC, c = t % CC;
    float s = __ldg(bl + c);
    const float* pr = g_pool + g * HH;
    #pragma unroll 8
    for (int h = 0; h < HH; ++h)
        s += pr[h] * __ldg(Wl + h * CC + c);
    out[t] = s;
}

// ---------------- launch ----------------
extern "C" void kernel_launch(void* const* d_in, const int* in_sizes, int n_in,
                              void* d_out, int out_size) {
    const float* x    = (const float*)d_in[0];
    const int*   ei   = (const int*)d_in[1];     // [2,E]
    const int*   batch= (const int*)d_in[2];
    const float* W1   = (const float*)d_in[3];
    const float* b1   = (const float*)d_in[4];
    const float* W2   = (const float*)d_in[5];
    const float* b2   = (const float*)d_in[6];
    const float* W3   = (const float*)d_in[7];
    const float* b3   = (const float*)d_in[8];
    const float* Wl   = (const float*)d_in[9];
    const float* bl   = (const float*)d_in[10];
    float* out = (float*)d_out;

    const int* erow = ei;        // sources
    const int* ecol = ei + EE;   // destinations

    float *hA, *hB;
    cudaGetSymbolAddress((void**)&hA, g_hA);
    cudaGetSymbolAddress((void**)&hB, g_hB);

    static bool attr_set = false;
    const int gemm_smem = (HH * HH + GEMM_ROWS * HH) * sizeof(float);   // 96 KB
    cudaFuncSetAttribute(gemm_kernel, cudaFuncAttributeMaxDynamicSharedMemorySize, gemm_smem);
    (void)attr_set;

    const int nblkN = (NN + 255) / 256;
    const int nblkE = (EE + 255) / 256;
    const int nwarpblk = (NN + 7) / 8;          // warp-per-node, 8 warps/block
    const int ngemm = (NN + GEMM_ROWS - 1) / GEMM_ROWS;

    init_kernel<<<nblkN, 256>>>();
    deg_kernel<<<nblkE, 256>>>(ecol);
    dinv_kernel<<<nblkN, 256>>>(batch);
    scan_kernel<<<1, 1024>>>();
    fill_kernel<<<nblkE, 256>>>(erow, ecol);

    layer1_kernel<<<nwarpblk, 256>>>(x, W1, b1);                 // -> g_hA (h1)
    gemm_kernel<<<ngemm, 256, gemm_smem>>>(hA, W2, hB);          // h1 @ W2 -> g_hB
    prop_kernel<true><<<nwarpblk, 256>>>(hB, hA, b2);            // -> g_hA (h2)
    gemm_kernel<<<ngemm, 256, gemm_smem>>>(hA, W3, hB);          // h2 @ W3 -> g_hB
    prop_kernel<false><<<nwarpblk, 256>>>(hB, hA, b3);           // -> g_hA (h3)
    pool_kernel<<<GG, 256>>>();
    final_kernel<<<1, 512>>>(Wl, bl, out);
}

// round 4
// speedup vs baseline: 1.3945x; 1.3945x over previous
#include <cuda_runtime.h>
#include <cuda_bf16.h>

#define NN 100000
#define EE 640000
#define HH 128
#define GG 64
#define CC 7

#define SCHUNK 256
#define SBLOCKS ((NN + SCHUNK - 1) / SCHUNK)   // 391

// ---------------- device scratch (no allocation allowed) ----------------
__device__ int   g_deg[NN];
__device__ float g_dinv[NN];
__device__ int   g_rowptr[NN + 1];
__device__ int   g_cursor[NN];
__device__ int   g_src[EE];
__device__ float g_w[EE];
__device__ float g_hA[(size_t)NN * HH];
__device__ float g_hB[(size_t)NN * HH];
__device__ float g_pool[GG * HH];
__device__ int   g_cnt[GG];
__device__ int   g_blksum[SBLOCKS];
__device__ int   g_blkoff[SBLOCKS];

// ---------------- helpers ----------------
__device__ __forceinline__ float4 f4_fma(float a, float4 v, float4 acc) {
    acc.x += a * v.x; acc.y += a * v.y; acc.z += a * v.z; acc.w += a * v.w;
    return acc;
}

// ---------------- init: deg=1 (self loop), cnt=0 ----------------
__global__ void init_kernel() {
    int i = blockIdx.x * blockDim.x + threadIdx.x;
    if (i < NN) g_deg[i] = 1;
    if (i < GG) g_cnt[i] = 0;
}

// ---------------- in-degree count ----------------
__global__ void deg_kernel(const int* __restrict__ col) {
    int e = blockIdx.x * blockDim.x + threadIdx.x;
    if (e < EE) atomicAdd(&g_deg[col[e]], 1);
}

// ---------------- dinv + per-graph node counts ----------------
__global__ void dinv_kernel(const int* __restrict__ batch) {
    int i = blockIdx.x * blockDim.x + threadIdx.x;
    if (i < NN) {
        g_dinv[i] = rsqrtf((float)g_deg[i]);
        atomicAdd(&g_cnt[batch[i]], 1);
    }
}

// ---------------- multi-block scan, phase A: per-block sums ----------------
__global__ void scanA_kernel() {
    int i = blockIdx.x * SCHUNK + threadIdx.x;
    int v = (i < NN) ? (g_deg[i] - 1) : 0;
    #pragma unroll
    for (int off = 16; off > 0; off >>= 1)
        v += __shfl_xor_sync(0xffffffffu, v, off);
    __shared__ int ws[8];
    int lane = threadIdx.x & 31, wid = threadIdx.x >> 5;
    if (lane == 0) ws[wid] = v;
    __syncthreads();
    if (threadIdx.x == 0) {
        int s = 0;
        #pragma unroll
        for (int j = 0; j < 8; ++j) s += ws[j];
        g_blksum[blockIdx.x] = s;
    }
}

// ---------------- phase B: scan the 391 block sums (one small block) ----------------
__global__ void scanB_kernel() {
    __shared__ int sm[512];
    int t = threadIdx.x;
    int v = (t < SBLOCKS) ? g_blksum[t] : 0;
    sm[t] = v;
    __syncthreads();
    #pragma unroll
    for (int off = 1; off < 512; off <<= 1) {
        int u = (t >= off) ? sm[t - off] : 0;
        __syncthreads();
        sm[t] += u;
        __syncthreads();
    }
    if (t < SBLOCKS) g_blkoff[t] = sm[t] - v;       // exclusive
    if (t == SBLOCKS - 1) g_rowptr[NN] = sm[t];     // grand total
}

// ---------------- phase C: local exclusive scan + offset -> rowptr/cursor ----------------
__global__ void scanC_kernel() {
    int i = blockIdx.x * SCHUNK + threadIdx.x;
    int v = (i < NN) ? (g_deg[i] - 1) : 0;
    int lane = threadIdx.x & 31, wid = threadIdx.x >> 5;
    int inc = v;
    #pragma unroll
    for (int off = 1; off <= 16; off <<= 1) {
        int n = __shfl_up_sync(0xffffffffu, inc, off);
        if (lane >= off) inc += n;
    }
    __shared__ int ws[8];
    if (lane == 31) ws[wid] = inc;
    __syncthreads();
    if (threadIdx.x == 0) {
        int run = 0;
        #pragma unroll
        for (int j = 0; j < 8; ++j) { int t = ws[j]; ws[j] = run; run += t; }
    }
    __syncthreads();
    int ex = inc - v + ws[wid] + g_blkoff[blockIdx.x];
    if (i < NN) { g_rowptr[i] = ex; g_cursor[i] = ex; }
}

// ---------------- CSR fill (bucket by destination) ----------------
__global__ void fill_kernel(const int* __restrict__ rowi, const int* __restrict__ coli) {
    int e = blockIdx.x * blockDim.x + threadIdx.x;
    if (e >= EE) return;
    int r = rowi[e], c = coli[e];
    int p = atomicAdd(&g_cursor[c], 1);
    g_src[p] = r;
    g_w[p]   = g_dinv[r] * g_dinv[c];
}

// ---------------- layer 1: scalar aggregation + outer product with W1 ----------------
__global__ void layer1_kernel(const float* __restrict__ x,
                              const float* __restrict__ W1,
                              const float* __restrict__ b1) {
    int warp = (blockIdx.x * blockDim.x + threadIdx.x) >> 5;
    int lane = threadIdx.x & 31;
    if (warp >= NN) return;
    const int i = warp;
    int ps = g_rowptr[i], pe = g_rowptr[i + 1];
    float s = 0.f;
    for (int p = ps + lane; p < pe; p += 32)
        s += g_w[p] * __ldg(x + g_src[p]);
    #pragma unroll
    for (int off = 16; off > 0; off >>= 1)
        s += __shfl_xor_sync(0xffffffffu, s, off);
    float di = g_dinv[i];
    s += di * di * __ldg(x + i);       // self loop
    float4 wv = ((const float4*)W1)[lane];
    float4 bv = ((const float4*)b1)[lane];
    float4 o;
    o.x = fmaxf(s * wv.x + bv.x, 0.f);
    o.y = fmaxf(s * wv.y + bv.y, 0.f);
    o.z = fmaxf(s * wv.z + bv.z, 0.f);
    o.w = fmaxf(s * wv.w + bv.w, 0.f);
    *(float4*)(g_hA + (size_t)i * HH + lane * 4) = o;
}

// ---------------- GEMM: C[N,128] = A[N,128] @ W[128,128]  (fp32, register-blocked) ----------------
#define GEMM_ROWS 64
#define TM 8
__global__ __launch_bounds__(256) void gemm_kernel(const float* __restrict__ A,
                                                   const float* __restrict__ W,
                                                   float* __restrict__ Cout) {
    extern __shared__ float sm[];
    float* Wsh = sm;                 // 128*128
    float* Ash = sm + HH * HH;       // 64*128
    const int tid = threadIdx.x;
    const float4* W4 = (const float4*)W;
    float4* Wsh4 = (float4*)Wsh;
    #pragma unroll
    for (int i = tid; i < HH * HH / 4; i += 256) Wsh4[i] = W4[i];
    const int block_row = blockIdx.x * GEMM_ROWS;
    const float4* A4 = (const float4*)(A + (size_t)block_row * HH);
    float4* Ash4 = (float4*)Ash;
    #pragma unroll
    for (int i = tid; i < GEMM_ROWS * HH / 4; i += 256) {
        int r = i / (HH / 4);
        Ash4[i] = (block_row + r < NN) ? A4[i] : make_float4(0.f, 0.f, 0.f, 0.f);
    }
    __syncthreads();

    const int ty = tid >> 5;
    const int tx = tid & 31;
    float4 acc[TM];
    #pragma unroll
    for (int i = 0; i < TM; ++i) acc[i] = make_float4(0.f, 0.f, 0.f, 0.f);
    const float* arow = Ash + (ty * TM) * HH;
    #pragma unroll 4
    for (int k = 0; k < HH; ++k) {
        float4 w = *(const float4*)(Wsh + k * HH + tx * 4);
        #pragma unroll
        for (int i = 0; i < TM; ++i) {
            float a = arow[i * HH + k];   // warp-broadcast LDS
            acc[i] = f4_fma(a, w, acc[i]);
        }
    }
    #pragma unroll
    for (int i = 0; i < TM; ++i) {
        int r = block_row + ty * TM + i;
        if (r < NN) *(float4*)(Cout + (size_t)r * HH + tx * 4) = acc[i];
    }
}

// ---------------- propagation: out[i] = relu?( sum_e w_e * hin[src] + dinv_i^2 * hin[i] + b ) ----------------
template <bool RELU>
__global__ void prop_kernel(const float* __restrict__ hin,
                            float* __restrict__ hout,
                            const float* __restrict__ bias) {
    int warp = (blockIdx.x * blockDim.x + threadIdx.x) >> 5;
    int lane = threadIdx.x & 31;
    if (warp >= NN) return;
    const int i = warp;
    const float di = g_dinv[i];
    float4 self = *(const float4*)(hin + (size_t)i * HH + lane * 4);
    const float w0 = di * di;
    float4 acc;
    acc.x = w0 * self.x; acc.y = w0 * self.y; acc.z = w0 * self.z; acc.w = w0 * self.w;
    int p = g_rowptr[i];
    const int pe = g_rowptr[i + 1];
    for (; p + 3 < pe; p += 4) {
        int s0 = g_src[p], s1 = g_src[p + 1], s2 = g_src[p + 2], s3 = g_src[p + 3];
        float wa = g_w[p], wb = g_w[p + 1], wc = g_w[p + 2], wd = g_w[p + 3];
        float4 v0 = *(const float4*)(hin + (size_t)s0 * HH + lane * 4);
        float4 v1 = *(const float4*)(hin + (size_t)s1 * HH + lane * 4);
        float4 v2 = *(const float4*)(hin + (size_t)s2 * HH + lane * 4);
        float4 v3 = *(const float4*)(hin + (size_t)s3 * HH + lane * 4);
        acc = f4_fma(wa, v0, acc);
        acc = f4_fma(wb, v1, acc);
        acc = f4_fma(wc, v2, acc);
        acc = f4_fma(wd, v3, acc);
    }
    for (; p < pe; ++p) {
        int s0 = g_src[p];
        float wa = g_w[p];
        float4 v0 = *(const float4*)(hin + (size_t)s0 * HH + lane * 4);
        acc = f4_fma(wa, v0, acc);
    }
    float4 b = ((const float4*)bias)[lane];
    acc.x += b.x; acc.y += b.y; acc.z += b.z; acc.w += b.w;
    if (RELU) {
        acc.x = fmaxf(acc.x, 0.f); acc.y = fmaxf(acc.y, 0.f);
        acc.z = fmaxf(acc.z, 0.f); acc.w = fmaxf(acc.w, 0.f);
    }
    *(float4*)(hout + (size_t)i * HH + lane * 4) = acc;
}

// ---------------- mean pool per graph (batch is sorted -> contiguous ranges) ----------------
__global__ void pool_kernel() {
    const int g = blockIdx.x;
    int start = 0;
    #pragma unroll
    for (int j = 0; j < GG; ++j) if (j < g) start += g_cnt[j];
    const int cntg = g_cnt[g];
    const int t = threadIdx.x;          // 256
    const int col = t & 127;
    const int half = t >> 7;
    float s = 0.f;
    for (int r = start + half; r < start + cntg; r += 2)
        s += g_hA[(size_t)r * HH + col];
    __shared__ float red[256];
    red[t] = s;
    __syncthreads();
    if (half == 0) {
        float tot = red[t] + red[t + 128];
        g_pool[g * HH + col] = tot / fmaxf((float)cntg, 1.f);
    }
}

// ---------------- final linear: out[G,C] = pool @ Wl + bl ----------------
__global__ void final_kernel(const float* __restrict__ Wl,
                             const float* __restrict__ bl,
                             float* __restrict__ out) {
    int t = threadIdx.x;
    if (t >= GG * CC) return;
    int g = t / CC, c = t % CC;
    float s = __ldg(bl + c);
    const float* pr = g_pool + g * HH;
    #pragma unroll 8
    for (int h = 0; h < HH; ++h)
        s += pr[h] * __ldg(Wl + h * CC + c);
    out[t] = s;
}

// ---------------- launch ----------------
extern "C" void kernel_launch(void* const* d_in, const int* in_sizes, int n_in,
                              void* d_out, int out_size) {
    const float* x    = (const float*)d_in[0];
    const int*   ei   = (const int*)d_in[1];     // [2,E]
    const int*   batch= (const int*)d_in[2];
    const float* W1   = (const float*)d_in[3];
    const float* b1   = (const float*)d_in[4];
    const float* W2   = (const float*)d_in[5];
    const float* b2   = (const float*)d_in[6];
    const float* W3   = (const float*)d_in[7];
    const float* b3   = (const float*)d_in[8];
    const float* Wl   = (const float*)d_in[9];
    const float* bl   = (const float*)d_in[10];
    float* out = (float*)d_out;

    const int* erow = ei;        // sources
    const int* ecol = ei + EE;   // destinations

    float *hA, *hB;
    cudaGetSymbolAddress((void**)&hA, g_hA);
    cudaGetSymbolAddress((void**)&hB, g_hB);

    const int gemm_smem = (HH * HH + GEMM_ROWS * HH) * sizeof(float);   // 96 KB
    cudaFuncSetAttribute(gemm_kernel, cudaFuncAttributeMaxDynamicSharedMemorySize, gemm_smem);

    const int nblkN = (NN + 255) / 256;
    const int nblkE = (EE + 255) / 256;
    const int nwarpblk = (NN + 7) / 8;          // warp-per-node, 8 warps/block
    const int ngemm = (NN + GEMM_ROWS - 1) / GEMM_ROWS;

    init_kernel<<<nblkN, 256>>>();
    deg_kernel<<<nblkE, 256>>>(ecol);
    dinv_kernel<<<nblkN, 256>>>(batch);
    scanA_kernel<<<SBLOCKS, SCHUNK>>>();
    scanB_kernel<<<1, 512>>>();
    scanC_kernel<<<SBLOCKS, SCHUNK>>>();
    fill_kernel<<<nblkE, 256>>>(erow, ecol);

    layer1_kernel<<<nwarpblk, 256>>>(x, W1, b1);                 // -> g_hA (h1)
    gemm_kernel<<<ngemm, 256, gemm_smem>>>(hA, W2, hB);          // h1 @ W2 -> g_hB
    prop_kernel<true><<<nwarpblk, 256>>>(hB, hA, b2);            // -> g_hA (h2)
    gemm_kernel<<<ngemm, 256, gemm_smem>>>(hA, W3, hB);          // h2 @ W3 -> g_hB
    prop_kernel<false><<<nwarpblk, 256>>>(hB, hA, b3);           // -> g_hA (h3)
    pool_kernel<<<GG, 256>>>();
    final_kernel<<<1, 512>>>(Wl, bl, out);
}